// round 9
// baseline (speedup 1.0000x reference)
#include <cuda_runtime.h>

#define T_LEN   1000
#define NB      4
#define GRIDB   128
#define THREADS 512

typedef unsigned long long ull;

__device__ float g_xg[512 * T_LEN * 256];   // precomputed input projections (+biases)

__device__ __forceinline__ ull fma2(ull a, ull b, ull c) {
    ull d;
    asm("fma.rn.f32x2 %0, %1, %2, %3;" : "=l"(d) : "l"(a), "l"(b), "l"(c));
    return d;
}
__device__ __forceinline__ ull pack2(float lo, float hi) {
    ull d;
    asm("mov.b64 %0, {%1, %2};" : "=l"(d) : "f"(lo), "f"(hi));
    return d;
}
__device__ __forceinline__ float hadd(ull a) {
    float lo, hi;
    asm("mov.b64 {%0, %1}, %2;" : "=f"(lo), "=f"(hi) : "l"(a));
    return lo + hi;
}
__device__ __forceinline__ float tanhap(float x) {
    float y;
    asm("tanh.approx.f32 %0, %1;" : "=f"(y) : "f"(x));
    return y;
}
__device__ __forceinline__ float sigap(float x) {
    return fmaf(0.5f, tanhap(0.5f * x), 0.5f);
}

// ---------------- pass 1: xg[b][t][j] = b_ih1[j]+b_hh1[j] + sum_k w_ih1[j][k]*x[b][k][t]
#define XTILE 50
extern "C" __global__ void __launch_bounds__(256)
xg_kernel(const float* __restrict__ x, const float* __restrict__ w_ih1,
          const float* __restrict__ b_ih1, const float* __restrict__ b_hh1)
{
    __shared__ float xt[26 * XTILE];
    const int tt = blockIdx.x;          // t-tile (0..19)
    const int b  = blockIdx.y;          // batch
    const int j  = threadIdx.x;         // gate row 0..255
    const int t0 = tt * XTILE;

    const float* xb = x + (size_t)b * 26 * T_LEN;
    for (int idx = j; idx < 26 * XTILE; idx += 256) {
        const int k = idx / XTILE, i = idx - k * XTILE;
        xt[idx] = xb[k * T_LEN + t0 + i];
    }
    float w[26];
    #pragma unroll
    for (int k = 0; k < 26; ++k) w[k] = w_ih1[j * 26 + k];
    const float bias = b_ih1[j] + b_hh1[j];
    __syncthreads();

    float* og = g_xg + ((size_t)b * T_LEN + t0) * 256 + j;
    #pragma unroll 2
    for (int i = 0; i < XTILE; ++i) {
        float a = bias;
        #pragma unroll
        for (int k = 0; k < 26; ++k) a = fmaf(w[k], xt[k * XTILE + i], a);
        og[(size_t)i * 256] = a;
    }
}

// ---------------- pass 2: persistent recurrent kernel ----------------
// warps 0..7  : LSTM1. thread (n, kq): lane = nloc*4+kq, n = wid*8+nloc (0..63),
//               kq-quarter (16 floats) of h1. W = 4 gates x 8 ull.
// warps 8..15 : LSTM2. thread (n, ks): lane = nloc*8+ks, n = (wid-8)*4+nloc (0..31),
//               ks-eighth (12 floats) of [h1(64)|h2(32)]. W = 4 gates x 6 ull.
// After butterfly reduce, one lane per (n,b) holds all 4 gate sums and does the
// c/h update in registers. One __syncthreads per step; ping-pong v buffers.
// v1: batch stride 88, unit n at (n>>4)*20+(n&15)  -> reads & stores conflict-free.
// v2: batch stride 104, [h1(64)|h2(32)]            -> reads & stores conflict-free.
extern "C" __global__ void __launch_bounds__(THREADS, 1)
lstm_kernel(const float* __restrict__ w_hh1,
            const float* __restrict__ w_ih2, const float* __restrict__ w_hh2,
            const float* __restrict__ b_ih2, const float* __restrict__ b_hh2,
            const float* __restrict__ w_fc1, const float* __restrict__ b_fc1,
            const float* __restrict__ w_fc2, const float* __restrict__ b_fc2,
            float* __restrict__ out)
{
    __shared__ __align__(16) float v1s[2][NB * 88];
    __shared__ __align__(16) float v2s[2][NB * 104];
    __shared__ float fcs[64];

    const int tid  = threadIdx.x;
    const int b0   = blockIdx.x * NB;
    const int wid  = tid >> 5;
    const int lane = tid & 31;
    const bool is1 = wid < 8;

    // LSTM1 mapping
    const int kq   = lane & 3;
    const int n1   = wid * 8 + (lane >> 2);
    const int q0   = kq & 1, q1 = (kq >> 1) & 1;
    // LSTM2 mapping
    const int ks   = lane & 7;
    const int n2   = (wid - 8) * 4 + (lane >> 3);
    const int ks0  = ks & 1, ks1 = (ks >> 1) & 1, ks2 = (ks >> 2) & 1;
    const int bb2  = (ks2 << 1) | ks1;          // batch owned after reduce

    // ----- per-thread weights -----
    ull W[32];
    if (is1) {
        #pragma unroll
        for (int g = 0; g < 4; ++g) {
            const float* wr = w_hh1 + (g * 64 + n1) * 64 + kq * 16;
            #pragma unroll
            for (int j = 0; j < 8; ++j) W[g * 8 + j] = pack2(wr[2 * j], wr[2 * j + 1]);
        }
    } else {
        #pragma unroll
        for (int g = 0; g < 4; ++g) {
            #pragma unroll
            for (int j = 0; j < 6; ++j) {
                const int kk = ks * 12 + 2 * j;        // even, never straddles 64
                float lo, hi;
                if (kk < 64) {
                    lo = w_ih2[(g * 32 + n2) * 64 + kk];
                    hi = w_ih2[(g * 32 + n2) * 64 + kk + 1];
                } else {
                    lo = w_hh2[(g * 32 + n2) * 32 + kk - 64];
                    hi = w_hh2[(g * 32 + n2) * 32 + kk - 63];
                }
                W[g * 6 + j] = pack2(lo, hi);
            }
        }
        #pragma unroll
        for (int j = 24; j < 32; ++j) W[j] = 0;
    }
    float bias2[4];
    if (!is1) {
        #pragma unroll
        for (int g = 0; g < 4; ++g) bias2[g] = b_ih2[g * 32 + n2] + b_hh2[g * 32 + n2];
    } else {
        bias2[0] = bias2[1] = bias2[2] = bias2[3] = 0.f;
    }

    for (int e = tid; e < 2 * NB * 88; e += THREADS)  ((float*)v1s)[e] = 0.f;
    for (int e = tid; e < 2 * NB * 104; e += THREADS) ((float*)v2s)[e] = 0.f;

    // xg pointers (LSTM1: batch kq, unit n1; value at [t][g*64+n1])
    const int BS = T_LEN * 256;                 // batch stride (floats, fits int)
    const float* xq = g_xg + (size_t)(b0 + kq) * BS + n1;
    float xr[4];
    if (is1) {
        #pragma unroll
        for (int g = 0; g < 4; ++g) xr[g] = xq[g * 64];
    }

    float c = 0.f;
    __syncthreads();

    // iter t: LSTM1 computes h1(t) (t<T_LEN); LSTM2 computes h2(t-1) (t>0).
    #pragma unroll 1
    for (int t = 0; t <= T_LEN; ++t) {
        const int cur = t & 1, nxt = cur ^ 1;
        if (is1) {
            if (t < T_LEN) {
                const int tp = (t + 1 < T_LEN) ? t + 1 : T_LEN - 1;
                float nx[4];
                #pragma unroll
                for (int g = 0; g < 4; ++g) nx[g] = xq[tp * 256 + g * 64];

                ull A[16];
                #pragma unroll
                for (int i = 0; i < 16; ++i) A[i] = 0;
                const float* vb = v1s[cur] + kq * 20;
                #pragma unroll
                for (int b = 0; b < 4; ++b) {
                    const ulonglong2 ua = *(const ulonglong2*)(vb + b * 88 + 0);
                    const ulonglong2 ub = *(const ulonglong2*)(vb + b * 88 + 4);
                    const ulonglong2 uc = *(const ulonglong2*)(vb + b * 88 + 8);
                    const ulonglong2 ud = *(const ulonglong2*)(vb + b * 88 + 12);
                    #pragma unroll
                    for (int g = 0; g < 4; ++g) {
                        ull a = A[g * 4 + b];
                        a = fma2(W[g * 8 + 0], ua.x, a); a = fma2(W[g * 8 + 1], ua.y, a);
                        a = fma2(W[g * 8 + 2], ub.x, a); a = fma2(W[g * 8 + 3], ub.y, a);
                        a = fma2(W[g * 8 + 4], uc.x, a); a = fma2(W[g * 8 + 5], uc.y, a);
                        a = fma2(W[g * 8 + 6], ud.x, a); a = fma2(W[g * 8 + 7], ud.y, a);
                        A[g * 4 + b] = a;
                    }
                }
                float fin[4];
                #pragma unroll
                for (int g = 0; g < 4; ++g) {
                    const float s0 = hadd(A[g * 4 + 0]), s1 = hadd(A[g * 4 + 1]);
                    const float s2 = hadd(A[g * 4 + 2]), s3 = hadd(A[g * 4 + 3]);
                    const float kp0 = q0 ? s1 : s0, sd0 = q0 ? s0 : s1;
                    const float kp1 = q0 ? s3 : s2, sd1 = q0 ? s2 : s3;
                    const float k10 = kp0 + __shfl_xor_sync(0xffffffffu, sd0, 1);
                    const float k11 = kp1 + __shfl_xor_sync(0xffffffffu, sd1, 1);
                    const float kp = q1 ? k11 : k10, sd = q1 ? k10 : k11;
                    fin[g] = kp + __shfl_xor_sync(0xffffffffu, sd, 2);
                }
                const float gi = sigap(fin[0] + xr[0]);
                const float gf = sigap(fin[1] + xr[1]);
                const float gg = tanhap(fin[2] + xr[2]);
                const float go = sigap(fin[3] + xr[3]);
                c = gf * c + gi * gg;
                const float h = go * tanhap(c);
                v1s[nxt][kq * 88 + ((n1 >> 4) * 20) + (n1 & 15)] = h;
                v2s[nxt][kq * 104 + n1] = h;
                #pragma unroll
                for (int g = 0; g < 4; ++g) xr[g] = nx[g];
            }
        } else if (t > 0) {
            ull A[16];
            #pragma unroll
            for (int i = 0; i < 16; ++i) A[i] = 0;
            const float* vb = v2s[cur] + ks * 12;
            #pragma unroll
            for (int b = 0; b < 4; ++b) {
                const ulonglong2 ua = *(const ulonglong2*)(vb + b * 104 + 0);
                const ulonglong2 ub = *(const ulonglong2*)(vb + b * 104 + 4);
                const ulonglong2 uc = *(const ulonglong2*)(vb + b * 104 + 8);
                #pragma unroll
                for (int g = 0; g < 4; ++g) {
                    ull a = A[g * 4 + b];
                    a = fma2(W[g * 6 + 0], ua.x, a); a = fma2(W[g * 6 + 1], ua.y, a);
                    a = fma2(W[g * 6 + 2], ub.x, a); a = fma2(W[g * 6 + 3], ub.y, a);
                    a = fma2(W[g * 6 + 4], uc.x, a); a = fma2(W[g * 6 + 5], uc.y, a);
                    A[g * 4 + b] = a;
                }
            }
            float fin[4];
            #pragma unroll
            for (int g = 0; g < 4; ++g) {
                const float s0 = hadd(A[g * 4 + 0]), s1 = hadd(A[g * 4 + 1]);
                const float s2 = hadd(A[g * 4 + 2]), s3 = hadd(A[g * 4 + 3]);
                // lvl1 (xor 4): keep batches with b1 == ks2
                const float ta = (ks2 ? s2 : s0) + __shfl_xor_sync(0xffffffffu, ks2 ? s0 : s2, 4);
                const float tb = (ks2 ? s3 : s1) + __shfl_xor_sync(0xffffffffu, ks2 ? s1 : s3, 4);
                // lvl2 (xor 2): keep b0 == ks1
                const float u = (ks1 ? tb : ta) + __shfl_xor_sync(0xffffffffu, ks1 ? ta : tb, 2);
                // lvl3 (xor 1): full reduce
                fin[g] = u + __shfl_xor_sync(0xffffffffu, u, 1);
            }
            const float gi = sigap(fin[0] + bias2[0]);
            const float gf = sigap(fin[1] + bias2[1]);
            const float gg = tanhap(fin[2] + bias2[2]);
            const float go = sigap(fin[3] + bias2[3]);
            c = gf * c + gi * gg;
            const float h2v = go * tanhap(c);
            if (ks0 == 0) v2s[nxt][bb2 * 104 + 64 + n2] = h2v;
        }
        __syncthreads();        // nxt complete; cur reusable
    }

    // ----- FC head on final h2 = v2s[1][b][64..95] -----
    if (tid < 64) {
        const int b = tid >> 4, f = tid & 15;
        float a = __ldg(b_fc1 + f);
        #pragma unroll
        for (int k = 0; k < 32; ++k)
            a += __ldg(w_fc1 + f * 32 + k) * v2s[1][b * 104 + 64 + k];
        fcs[b * 16 + f] = fmaxf(a, 0.f);
    }
    __syncthreads();
    if (tid < 40) {
        const int b = tid / 10, o = tid - b * 10;
        float a = __ldg(b_fc2 + o);
        #pragma unroll
        for (int k = 0; k < 16; ++k)
            a += __ldg(w_fc2 + o * 16 + k) * fcs[b * 16 + k];
        out[(b0 + b) * 10 + o] = a;
    }
}

extern "C" void kernel_launch(void* const* d_in, const int* in_sizes, int n_in,
                              void* d_out, int out_size) {
    (void)in_sizes; (void)n_in; (void)out_size;
    xg_kernel<<<dim3(20, 512), 256>>>(
        (const float*)d_in[0],   // x
        (const float*)d_in[1],   // w_ih1
        (const float*)d_in[3],   // b_ih1
        (const float*)d_in[4]);  // b_hh1
    lstm_kernel<<<GRIDB, THREADS>>>(
        (const float*)d_in[2],   // w_hh1
        (const float*)d_in[5],   // w_ih2
        (const float*)d_in[6],   // w_hh2
        (const float*)d_in[7],   // b_ih2
        (const float*)d_in[8],   // b_hh2
        (const float*)d_in[9],   // w_fc1
        (const float*)d_in[10],  // b_fc1
        (const float*)d_in[11],  // w_fc2
        (const float*)d_in[12],  // b_fc2
        (float*)d_out);
}

// round 10
// speedup vs baseline: 1.3094x; 1.3094x over previous
#include <cuda_runtime.h>

#define T_LEN   1000
#define NB      4
#define GRIDB   128
#define THREADS 384
#define RD      4          // h1 ring depth
#define RES     416        // ring entry stride (floats) = 4 * 104; 416 % 32 == 0
#define RBS     104        // ring batch stride (104 % 32 == 8)

typedef unsigned long long ull;

__device__ float g_xg[512 * T_LEN * 256];   // precomputed input projections (+biases)

__device__ __forceinline__ ull fma2(ull a, ull b, ull c) {
    ull d;
    asm("fma.rn.f32x2 %0, %1, %2, %3;" : "=l"(d) : "l"(a), "l"(b), "l"(c));
    return d;
}
__device__ __forceinline__ ull pack2(float lo, float hi) {
    ull d;
    asm("mov.b64 %0, {%1, %2};" : "=l"(d) : "f"(lo), "f"(hi));
    return d;
}
__device__ __forceinline__ float hadd(ull a) {
    float lo, hi;
    asm("mov.b64 {%0, %1}, %2;" : "=f"(lo), "=f"(hi) : "l"(a));
    return lo + hi;
}
__device__ __forceinline__ void unpack2(ull a, float& lo, float& hi) {
    asm("mov.b64 {%0, %1}, %2;" : "=f"(lo), "=f"(hi) : "l"(a));
}
__device__ __forceinline__ float tanhap(float x) {
    float y;
    asm("tanh.approx.f32 %0, %1;" : "=f"(y) : "f"(x));
    return y;
}
__device__ __forceinline__ float sigap(float x) {
    return fmaf(0.5f, tanhap(0.5f * x), 0.5f);
}

// ---------------- pass 1: xg[b][t][j] = b_ih1[j]+b_hh1[j] + sum_k w_ih1[j][k]*x[b][k][t]
// t processed in pairs with packed f32x2 FMAs.
#define XTILE 50
extern "C" __global__ void __launch_bounds__(256)
xg_kernel(const float* __restrict__ x, const float* __restrict__ w_ih1,
          const float* __restrict__ b_ih1, const float* __restrict__ b_hh1)
{
    __shared__ float xt[26 * XTILE];
    const int tt = blockIdx.x;          // t-tile (0..19)
    const int b  = blockIdx.y;          // batch
    const int j  = threadIdx.x;         // gate row 0..255
    const int t0 = tt * XTILE;

    const float* xb = x + (size_t)b * 26 * T_LEN;
    for (int idx = j; idx < 26 * XTILE; idx += 256) {
        const int k = idx / XTILE, i = idx - k * XTILE;
        xt[idx] = xb[k * T_LEN + t0 + i];
    }
    ull Wp[26];
    #pragma unroll
    for (int k = 0; k < 26; ++k) {
        const float w = w_ih1[j * 26 + k];
        Wp[k] = pack2(w, w);
    }
    const float bias = b_ih1[j] + b_hh1[j];
    const ull biasp = pack2(bias, bias);
    __syncthreads();

    float* og = g_xg + ((size_t)b * T_LEN + t0) * 256 + j;
    #pragma unroll 1
    for (int i = 0; i < XTILE; i += 2) {
        ull a = biasp;
        #pragma unroll
        for (int k = 0; k < 26; ++k) {
            const ull xv = *(const ull*)&xt[k * XTILE + i];   // 8B aligned (i, 50k even)
            a = fma2(Wp[k], xv, a);
        }
        float lo, hi;
        unpack2(a, lo, hi);
        og[(size_t)i * 256]       = lo;
        og[(size_t)(i + 1) * 256] = hi;
    }
}

// ---------------- pass 2: persistent recurrent kernel, DECOUPLED warp groups ------------
// Group 1 (warps 0..7, 256 thr, bar.sync 1): LSTM1. thread (n1, kq):
//   lane = nloc*4+kq, n1 = wid*8+nloc (0..63), kq-quarter (16 floats) of h1.
//   Own ping-pong v1s; writes h1(t) into ring entry t%RD. Publishes prod.
// Group 2 (warps 8..11, 128 thr, bar.sync 2): LSTM2. thread (n2, kq):
//   lane = nloc*4+kq, n2 = (wid-8)*8+nloc (0..31), kq-slice (24 floats) of [h1|h2].
//   Step s reads ring entry s%RD (h1(s) | h2(s-1)); writes h2(s) into entry (s+1)%RD.
//   Publishes cons. One-way dataflow L1 -> L2; bounded-queue spin flow control.
extern "C" __global__ void __launch_bounds__(THREADS, 1)
lstm_kernel(const float* __restrict__ w_hh1,
            const float* __restrict__ w_ih2, const float* __restrict__ w_hh2,
            const float* __restrict__ b_ih2, const float* __restrict__ b_hh2,
            const float* __restrict__ w_fc1, const float* __restrict__ b_fc1,
            const float* __restrict__ w_fc2, const float* __restrict__ b_fc2,
            float* __restrict__ out)
{
    __shared__ __align__(16) float v1s[2][NB * 88];
    __shared__ __align__(16) float ring[RD * RES];   // [entry][batch(104)] = h1(64)|h2(32)|pad
    __shared__ float fcs[64];
    __shared__ int prod_s, cons_s;

    const int tid  = threadIdx.x;
    const int b0   = blockIdx.x * NB;
    const int wid  = tid >> 5;
    const int lane = tid & 31;
    const bool is1 = wid < 8;
    const int kq   = lane & 3;
    const int nloc = lane >> 2;
    const int n1   = wid * 8 + nloc;                  // 0..63 (group 1)
    const int n2   = (wid - 8) * 8 + nloc;            // 0..31 (group 2)
    const int q0   = kq & 1, q1 = (kq >> 1) & 1;

    // ----- per-thread weights -----
    ull W[48];
    float bias2[4] = {0.f, 0.f, 0.f, 0.f};
    if (is1) {
        #pragma unroll
        for (int g = 0; g < 4; ++g) {
            const float* wr = w_hh1 + (g * 64 + n1) * 64 + kq * 16;
            #pragma unroll
            for (int j = 0; j < 8; ++j) W[g * 8 + j] = pack2(wr[2 * j], wr[2 * j + 1]);
        }
        #pragma unroll
        for (int j = 32; j < 48; ++j) W[j] = 0;
    } else {
        #pragma unroll
        for (int g = 0; g < 4; ++g) {
            #pragma unroll
            for (int j = 0; j < 12; ++j) {
                const int kk = kq * 24 + 2 * j;       // even; never straddles 64
                float lo, hi;
                if (kk < 64) {
                    lo = w_ih2[(g * 32 + n2) * 64 + kk];
                    hi = w_ih2[(g * 32 + n2) * 64 + kk + 1];
                } else {
                    lo = w_hh2[(g * 32 + n2) * 32 + kk - 64];
                    hi = w_hh2[(g * 32 + n2) * 32 + kk - 63];
                }
                W[g * 12 + j] = pack2(lo, hi);
            }
            bias2[g] = b_ih2[g * 32 + n2] + b_hh2[g * 32 + n2];
        }
    }

    for (int e = tid; e < 2 * NB * 88; e += THREADS) ((float*)v1s)[e] = 0.f;
    for (int e = tid; e < RD * RES; e += THREADS) ring[e] = 0.f;
    if (tid == 0) { prod_s = 0; cons_s = 0; }
    __syncthreads();

    if (is1) {
        // ===================== group 1: LSTM1 =====================
        const int BS = T_LEN * 256;
        const float* xq = g_xg + (size_t)(b0 + kq) * BS + n1;
        float xr[4];
        #pragma unroll
        for (int g = 0; g < 4; ++g) xr[g] = xq[g * 64];
        float c = 0.f;

        #pragma unroll 1
        for (int t = 0; t < T_LEN; ++t) {
            const int cur = t & 1, nxt = cur ^ 1;
            // ring slot t%RD: old h1(t-RD) must be consumed (L2 finished step t-RD)
            if (t >= RD) {
                while (*(volatile int*)&cons_s < t - RD + 1) {}
            }
            const int tp = (t + 1 < T_LEN) ? t + 1 : T_LEN - 1;
            float nx[4];
            #pragma unroll
            for (int g = 0; g < 4; ++g) nx[g] = xq[tp * 256 + g * 64];

            ull A[16];
            #pragma unroll
            for (int i = 0; i < 16; ++i) A[i] = 0;
            const float* vb = v1s[cur] + kq * 20;
            #pragma unroll
            for (int b = 0; b < 4; ++b) {
                const ulonglong2 ua = *(const ulonglong2*)(vb + b * 88 + 0);
                const ulonglong2 ub = *(const ulonglong2*)(vb + b * 88 + 4);
                const ulonglong2 uc = *(const ulonglong2*)(vb + b * 88 + 8);
                const ulonglong2 ud = *(const ulonglong2*)(vb + b * 88 + 12);
                #pragma unroll
                for (int g = 0; g < 4; ++g) {
                    ull a = A[g * 4 + b];
                    a = fma2(W[g * 8 + 0], ua.x, a); a = fma2(W[g * 8 + 1], ua.y, a);
                    a = fma2(W[g * 8 + 2], ub.x, a); a = fma2(W[g * 8 + 3], ub.y, a);
                    a = fma2(W[g * 8 + 4], uc.x, a); a = fma2(W[g * 8 + 5], uc.y, a);
                    a = fma2(W[g * 8 + 6], ud.x, a); a = fma2(W[g * 8 + 7], ud.y, a);
                    A[g * 4 + b] = a;
                }
            }
            float fin[4];
            #pragma unroll
            for (int g = 0; g < 4; ++g) {
                const float s0 = hadd(A[g * 4 + 0]), s1 = hadd(A[g * 4 + 1]);
                const float s2 = hadd(A[g * 4 + 2]), s3 = hadd(A[g * 4 + 3]);
                const float kp0 = q0 ? s1 : s0, sd0 = q0 ? s0 : s1;
                const float kp1 = q0 ? s3 : s2, sd1 = q0 ? s2 : s3;
                const float k10 = kp0 + __shfl_xor_sync(0xffffffffu, sd0, 1);
                const float k11 = kp1 + __shfl_xor_sync(0xffffffffu, sd1, 1);
                const float kp = q1 ? k11 : k10, sd = q1 ? k10 : k11;
                fin[g] = kp + __shfl_xor_sync(0xffffffffu, sd, 2);
            }
            const float gi = sigap(fin[0] + xr[0]);
            const float gf = sigap(fin[1] + xr[1]);
            const float gg = tanhap(fin[2] + xr[2]);
            const float go = sigap(fin[3] + xr[3]);
            c = gf * c + gi * gg;
            const float h = go * tanhap(c);
            v1s[nxt][kq * 88 + ((n1 >> 4) * 20) + (n1 & 15)] = h;
            ring[(t % RD) * RES + kq * RBS + n1] = h;
            #pragma unroll
            for (int g = 0; g < 4; ++g) xr[g] = nx[g];

            asm volatile("bar.sync 1, 256;" ::: "memory");
            if (tid == 0) *(volatile int*)&prod_s = t + 1;
        }
    } else {
        // ===================== group 2: LSTM2 =====================
        float c = 0.f;
        #pragma unroll 1
        for (int s = 0; s < T_LEN; ++s) {
            while (*(volatile int*)&prod_s < s + 1) {}
            ull A[16];
            #pragma unroll
            for (int i = 0; i < 16; ++i) A[i] = 0;
            const float* vb = ring + (s % RD) * RES + kq * 24;
            #pragma unroll
            for (int b = 0; b < 4; ++b) {
                const ulonglong2 ua = *(const ulonglong2*)(vb + b * RBS + 0);
                const ulonglong2 ub = *(const ulonglong2*)(vb + b * RBS + 4);
                const ulonglong2 uc = *(const ulonglong2*)(vb + b * RBS + 8);
                const ulonglong2 ud = *(const ulonglong2*)(vb + b * RBS + 12);
                const ulonglong2 ue = *(const ulonglong2*)(vb + b * RBS + 16);
                const ulonglong2 uf = *(const ulonglong2*)(vb + b * RBS + 20);
                #pragma unroll
                for (int g = 0; g < 4; ++g) {
                    ull a = A[g * 4 + b];
                    a = fma2(W[g * 12 + 0],  ua.x, a); a = fma2(W[g * 12 + 1],  ua.y, a);
                    a = fma2(W[g * 12 + 2],  ub.x, a); a = fma2(W[g * 12 + 3],  ub.y, a);
                    a = fma2(W[g * 12 + 4],  uc.x, a); a = fma2(W[g * 12 + 5],  uc.y, a);
                    a = fma2(W[g * 12 + 6],  ud.x, a); a = fma2(W[g * 12 + 7],  ud.y, a);
                    a = fma2(W[g * 12 + 8],  ue.x, a); a = fma2(W[g * 12 + 9],  ue.y, a);
                    a = fma2(W[g * 12 + 10], uf.x, a); a = fma2(W[g * 12 + 11], uf.y, a);
                    A[g * 4 + b] = a;
                }
            }
            float fin[4];
            #pragma unroll
            for (int g = 0; g < 4; ++g) {
                const float s0 = hadd(A[g * 4 + 0]), s1 = hadd(A[g * 4 + 1]);
                const float s2 = hadd(A[g * 4 + 2]), s3 = hadd(A[g * 4 + 3]);
                const float kp0 = q0 ? s1 : s0, sd0 = q0 ? s0 : s1;
                const float kp1 = q0 ? s3 : s2, sd1 = q0 ? s2 : s3;
                const float k10 = kp0 + __shfl_xor_sync(0xffffffffu, sd0, 1);
                const float k11 = kp1 + __shfl_xor_sync(0xffffffffu, sd1, 1);
                const float kp = q1 ? k11 : k10, sd = q1 ? k10 : k11;
                fin[g] = kp + __shfl_xor_sync(0xffffffffu, sd, 2);
            }
            const float gi = sigap(fin[0] + bias2[0]);
            const float gf = sigap(fin[1] + bias2[1]);
            const float gg = tanhap(fin[2] + bias2[2]);
            const float go = sigap(fin[3] + bias2[3]);
            c = gf * c + gi * gg;
            // h2(s) -> entry (s+1)%RD (consumed by own step s+1; FC reads entry T%RD)
            ring[((s + 1) % RD) * RES + kq * RBS + 64 + n2] = go * tanhap(c);

            asm volatile("bar.sync 2, 128;" ::: "memory");
            if (tid == 256) *(volatile int*)&cons_s = s + 1;
        }
    }
    __syncthreads();

    // ----- FC head on final h2 = ring entry (T_LEN % RD) = 0, h2 part -----
    if (tid < 64) {
        const int b = tid >> 4, f = tid & 15;
        float a = __ldg(b_fc1 + f);
        #pragma unroll
        for (int k = 0; k < 32; ++k)
            a += __ldg(w_fc1 + f * 32 + k) * ring[(T_LEN % RD) * RES + b * RBS + 64 + k];
        fcs[b * 16 + f] = fmaxf(a, 0.f);
    }
    __syncthreads();
    if (tid < 40) {
        const int b = tid / 10, o = tid - b * 10;
        float a = __ldg(b_fc2 + o);
        #pragma unroll
        for (int k = 0; k < 16; ++k)
            a += __ldg(w_fc2 + o * 16 + k) * fcs[b * 16 + k];
        out[(b0 + b) * 10 + o] = a;
    }
}

extern "C" void kernel_launch(void* const* d_in, const int* in_sizes, int n_in,
                              void* d_out, int out_size) {
    (void)in_sizes; (void)n_in; (void)out_size;
    xg_kernel<<<dim3(20, 512), 256>>>(
        (const float*)d_in[0],   // x
        (const float*)d_in[1],   // w_ih1
        (const float*)d_in[3],   // b_ih1
        (const float*)d_in[4]);  // b_hh1
    lstm_kernel<<<GRIDB, THREADS>>>(
        (const float*)d_in[2],   // w_hh1
        (const float*)d_in[5],   // w_ih2
        (const float*)d_in[6],   // w_hh2
        (const float*)d_in[7],   // b_ih2
        (const float*)d_in[8],   // b_hh2
        (const float*)d_in[9],   // w_fc1
        (const float*)d_in[10],  // b_fc1
        (const float*)d_in[11],  // w_fc2
        (const float*)d_in[12],  // b_fc2
        (float*)d_out);
}